// round 1
// baseline (speedup 1.0000x reference)
#include <cuda_runtime.h>

#define H 1024
#define W 2048
#define B 8
#define N 64

__global__ void zero_out_kernel(float* d_out) {
    d_out[0] = 0.0f;
}

// Grid: (N, B). Block (b, i) handles the row y_i of batch b, but only if i is
// the FIRST fixation index in batch b that maps to that row (dedup). It then
// replays all fixations of batch b in order to build the final fm row values
// and dots them with y_pred[b, 0, y, :], accumulating into d_out (scaled).
__global__ void spherical_nss_kernel(const float* __restrict__ y_pred,
                                     const float* __restrict__ fixations,
                                     const float* __restrict__ edge_vals,
                                     const int*   __restrict__ ker_ws,
                                     float* d_out) {
    const int b = blockIdx.y;
    const int i = blockIdx.x;
    const int tid = threadIdx.x;

    __shared__ int sxs[N];
    __shared__ int sys[N];
    __shared__ float sred[256];

    // Load and round fixations for this batch (round-half-to-even via rintf,
    // matching jnp.rint).
    if (tid < N) {
        float fx = fixations[(b * N + tid) * 2 + 0];
        float fy = fixations[(b * N + tid) * 2 + 1];
        sxs[tid] = (int)rintf(fx * (float)(W - 1));
        sys[tid] = (int)rintf(fy * (float)(H - 1));
    }
    __syncthreads();

    const int y = sys[i];
    // Dedup: only the first fixation index with this y processes the row.
    for (int j = 0; j < i; ++j) {
        if (sys[j] == y) return;
    }

    const bool pole = (y == 0) || (y == H - 1);
    const int   kw = ker_ws[y];
    const float ev = edge_vals[y];
    const float* row = y_pred + ((size_t)b * H + y) * W;

    float acc = 0.0f;
    if (pole) {
        // Whole row forced to 1.0
        for (int c = tid; c < W; c += blockDim.x) {
            acc += row[c];
        }
    } else {
        for (int c = tid; c < W; c += blockDim.x) {
            float v = 0.0f;
            // Replay fixations in scan order; later ones overwrite.
            #pragma unroll 4
            for (int n = 0; n < N; ++n) {
                if (sys[n] == y) {
                    int left = sxs[n] - (kw >> 1);
                    int off = (c - left) % W;
                    if (off < 0) off += W;
                    if (off < kw) {
                        v = (off == 0 || off == kw - 1) ? ev : 1.0f;
                    }
                }
            }
            acc += v * row[c];
        }
    }

    // Block tree reduction
    sred[tid] = acc;
    __syncthreads();
    for (int s = blockDim.x >> 1; s > 0; s >>= 1) {
        if (tid < s) sred[tid] += sred[tid + s];
        __syncthreads();
    }
    if (tid == 0) {
        // scale: (sum / num_fix) averaged over batches = 1/(N*B)
        atomicAdd(d_out, sred[0] * (1.0f / ((float)N * (float)B)));
    }
}

extern "C" void kernel_launch(void* const* d_in, const int* in_sizes, int n_in,
                              void* d_out, int out_size) {
    const float* y_pred    = (const float*)d_in[0];
    const float* fixations = (const float*)d_in[1];
    const float* edge_vals = (const float*)d_in[2];
    const int*   ker_ws    = (const int*)d_in[3];
    float* out = (float*)d_out;

    zero_out_kernel<<<1, 1>>>(out);
    dim3 grid(N, B);
    spherical_nss_kernel<<<grid, 256>>>(y_pred, fixations, edge_vals, ker_ws, out);
}

// round 2
// speedup vs baseline: 1.2434x; 1.2434x over previous
#include <cuda_runtime.h>

#define H 1024
#define W 2048
#define B 8
#define N 64

__global__ void zero_out_kernel(float* d_out) {
    d_out[0] = 0.0f;
}

// Grid: (N, B), one warp per block. Block (i, b) owns the row hit by fixation
// i of batch b, but only if i is the FIRST fixation in that batch mapping to
// that row (dedup via ballot mask). fm is zero outside fixation windows, so
// the dot product only visits covered columns:
//   - single fixation on the row (common): enumerate its kw window directly
//   - multiple fixations (rare): full-width replay over matched set, in scan
//     order (ascending n) so later fixations overwrite
//   - pole rows: entire row is 1.0 -> vectorized row sum
__global__ void __launch_bounds__(32)
spherical_nss_kernel(const float* __restrict__ y_pred,
                     const float* __restrict__ fixations,
                     const float* __restrict__ edge_vals,
                     const int*   __restrict__ ker_ws,
                     float* d_out) {
    const int b = blockIdx.y;
    const int i = blockIdx.x;
    const int l = threadIdx.x;

    __shared__ int sxs[N];
    __shared__ int sys[N];

    // Each lane rounds 2 fixations (round-half-to-even via rintf = jnp.rint).
    #pragma unroll
    for (int k = 0; k < 2; ++k) {
        int n = l + 32 * k;
        float fx = fixations[(b * N + n) * 2 + 0];
        float fy = fixations[(b * N + n) * 2 + 1];
        sxs[n] = (int)rintf(fx * (float)(W - 1));
        sys[n] = (int)rintf(fy * (float)(H - 1));
    }
    __syncwarp();

    const int y = sys[i];

    // 64-bit mask of fixations in this batch hitting row y.
    unsigned lo = __ballot_sync(0xffffffffu, sys[l] == y);
    unsigned hi = __ballot_sync(0xffffffffu, sys[l + 32] == y);
    unsigned long long mask = ((unsigned long long)hi << 32) | (unsigned long long)lo;

    // Dedup: bail if any earlier fixation already hit this row.
    unsigned long long below = (i == 0) ? 0ull : (mask & ((1ull << i) - 1ull));
    if (below) return;

    const float* row = y_pred + ((size_t)b * H + y) * W;
    float acc = 0.0f;

    if (y == 0 || y == H - 1) {
        // Pole: whole row forced to 1.0
        const float4* row4 = (const float4*)row;
        #pragma unroll 4
        for (int c = l; c < W / 4; c += 32) {
            float4 v = row4[c];
            acc += (v.x + v.y) + (v.z + v.w);
        }
    } else {
        const int   kw = ker_ws[y];
        const float ev = edge_vals[y];
        const int cnt = __popcll(mask);

        if (cnt == 1) {
            // Only fixation i covers this row: visit its kw columns directly.
            const int left = sxs[i] - (kw >> 1);
            for (int off = l; off < kw; off += 32) {
                int c = (left + off) % W;
                if (c < 0) c += W;
                float v = (off == 0 || off == kw - 1) ? ev : 1.0f;
                acc += v * row[c];
            }
        } else {
            // Rare: replay matched fixations in scan order across the row.
            for (int c = l; c < W; c += 32) {
                float v = 0.0f;
                unsigned long long m = mask;
                while (m) {
                    int n = __ffsll(m) - 1;  // ascending n = scan order
                    m &= m - 1;
                    int left = sxs[n] - (kw >> 1);
                    int off = (c - left) % W;
                    if (off < 0) off += W;
                    if (off < kw) {
                        v = (off == 0 || off == kw - 1) ? ev : 1.0f;
                    }
                }
                acc += v * row[c];
            }
        }
    }

    // Warp reduction + single atomic per surviving block.
    #pragma unroll
    for (int s = 16; s > 0; s >>= 1)
        acc += __shfl_down_sync(0xffffffffu, acc, s);
    if (l == 0)
        atomicAdd(d_out, acc * (1.0f / ((float)N * (float)B)));
}

extern "C" void kernel_launch(void* const* d_in, const int* in_sizes, int n_in,
                              void* d_out, int out_size) {
    const float* y_pred    = (const float*)d_in[0];
    const float* fixations = (const float*)d_in[1];
    const float* edge_vals = (const float*)d_in[2];
    const int*   ker_ws    = (const int*)d_in[3];
    float* out = (float*)d_out;

    zero_out_kernel<<<1, 1>>>(out);
    dim3 grid(N, B);
    spherical_nss_kernel<<<grid, 32>>>(y_pred, fixations, edge_vals, ker_ws, out);
}